// round 8
// baseline (speedup 1.0000x reference)
#include <cuda_runtime.h>
#include <cuda_fp16.h>

#define HD 128
#define NMAX 100000
#define EMAX 3200000
#define EPSBN 1e-5f

// ---------------- scratch (static device globals; no allocation) ----------------
__device__ __align__(16) float  d_h  [NMAX * HD];    // current node features
__device__ __align__(16) __half d_t1h[NMAX * HD];    // h @ W  (fp16 gather source)
__device__ __align__(16) float  d_t2 [NMAX * HD];    // aggregated
__device__ __align__(16) float  d_dinv [NMAX];       // deg^-1/2
__device__ __align__(16) float  d_dinv2[NMAX];       // deg^-1  (self-loop norm)
__device__ __align__(16) int    d_cnt [NMAX];        // in-degree histogram (excl. self loop)
__device__ __align__(16) int    d_fill[NMAX];        // CSR fill cursors
__device__ __align__(16) int    d_rowstart[NMAX + 4];
__device__ __align__(16) int    d_bsum[512];         // scan block partials
__device__ __align__(16) int    d_boff[512];         // scan block offsets
__device__ __align__(16) int    d_csr_srco[EMAX];    // src * 64 (half2 offset) per CSR slot
__device__ __align__(16) float  d_csr_norm[EMAX];    // edge norm per CSR slot
__device__ __align__(16) float  d_stats[2 * HD];     // [sum, sumsq]
__device__ __align__(16) float  d_scale[HD];
__device__ __align__(16) float  d_shift[HD];
__device__ __align__(16) float  d_pool[HD];

// ---------------- prep ----------------
__global__ void k_init(int n) {
    int i = blockIdx.x * blockDim.x + threadIdx.x;
    if (i < n) { d_cnt[i] = 0; d_fill[i] = 0; }
    if (i < 2 * HD) d_stats[i] = 0.0f;
    if (i < HD) d_pool[i] = 0.0f;
}

// edge_index is int32 on device (JAX default x64-disabled)
__global__ void k_count(const int* __restrict__ ei, int e) {
    int i = blockIdx.x * blockDim.x + threadIdx.x;
    if (i < e) atomicAdd(&d_cnt[ei[e + i]], 1);   // row 1 = dst
}

__global__ void k_dinv(int n) {
    int i = blockIdx.x * blockDim.x + threadIdx.x;
    if (i < n) {
        float deg = (float)(d_cnt[i] + 1);   // + self loop
        d_dinv[i]  = rsqrtf(deg);
        d_dinv2[i] = 1.0f / deg;
    }
}

// ---- parallel scan: phase 1, per-block reduce ----
__global__ void __launch_bounds__(256) k_scan1(int n) {
    __shared__ int s[256];
    int tid = threadIdx.x;
    int i = blockIdx.x * 256 + tid;
    s[tid] = (i < n) ? d_cnt[i] : 0;
    __syncthreads();
#pragma unroll
    for (int off = 128; off; off >>= 1) {
        if (tid < off) s[tid] += s[tid + off];
        __syncthreads();
    }
    if (tid == 0) d_bsum[blockIdx.x] = s[0];
}

// ---- phase 2: single-block scan of <=512 partials ----
__global__ void __launch_bounds__(512) k_scan2(int nblk, int n) {
    __shared__ int s[512];
    int tid = threadIdx.x;
    int v = (tid < nblk) ? d_bsum[tid] : 0;
    s[tid] = v;
    __syncthreads();
#pragma unroll
    for (int off = 1; off < 512; off <<= 1) {
        int t = (tid >= off) ? s[tid - off] : 0;
        __syncthreads();
        s[tid] += t;
        __syncthreads();
    }
    if (tid < nblk) d_boff[tid] = s[tid] - v;   // exclusive
    if (tid == 511) d_rowstart[n] = s[511];
}

// ---- phase 3: per-block local exclusive scan + offset ----
__global__ void __launch_bounds__(256) k_scan3(int n) {
    __shared__ int s[256];
    int tid = threadIdx.x;
    int i = blockIdx.x * 256 + tid;
    int v = (i < n) ? d_cnt[i] : 0;
    s[tid] = v;
    __syncthreads();
#pragma unroll
    for (int off = 1; off < 256; off <<= 1) {
        int t = (tid >= off) ? s[tid - off] : 0;
        __syncthreads();
        s[tid] += t;
        __syncthreads();
    }
    if (i < n) d_rowstart[i] = d_boff[blockIdx.x] + s[tid] - v;
}

__global__ void k_fill(const int* __restrict__ ei, int e) {
    int i = blockIdx.x * blockDim.x + threadIdx.x;
    if (i < e) {
        int s = ei[i];
        int d = ei[e + i];
        int pos = d_rowstart[d] + atomicAdd(&d_fill[d], 1);
        d_csr_srco[pos] = s * 64;              // half2 offset (64 half2 per row)
        d_csr_norm[pos] = d_dinv[s] * d_dinv[d];
    }
}

// ---------------- input layer: t2 = x @ in_W, fused BN stats ----------------
__global__ void __launch_bounds__(256) k_ingemm(const float* __restrict__ x,
                                                const float* __restrict__ W, int n) {
    __shared__ float ss[HD], sq[HD];
    int tid = threadIdx.x;
    if (tid < HD) { ss[tid] = 0.f; sq[tid] = 0.f; }
    __syncthreads();

    int idx = blockIdx.x * blockDim.x + tid;
    int i = idx >> 5, c4 = idx & 31;
    if (i < n) {
        const float* xr = x + i * 5;
        float x0 = xr[0], x1 = xr[1], x2 = xr[2], x3 = xr[3], x4 = xr[4];
        int c = c4 * 4;
        float4 o;
        o.x = x0*W[0*HD+c+0] + x1*W[1*HD+c+0] + x2*W[2*HD+c+0] + x3*W[3*HD+c+0] + x4*W[4*HD+c+0];
        o.y = x0*W[0*HD+c+1] + x1*W[1*HD+c+1] + x2*W[2*HD+c+1] + x3*W[3*HD+c+1] + x4*W[4*HD+c+1];
        o.z = x0*W[0*HD+c+2] + x1*W[1*HD+c+2] + x2*W[2*HD+c+2] + x3*W[3*HD+c+2] + x4*W[4*HD+c+2];
        o.w = x0*W[0*HD+c+3] + x1*W[1*HD+c+3] + x2*W[2*HD+c+3] + x3*W[3*HD+c+3] + x4*W[4*HD+c+3];
        __stcs((float4*)&d_t2[i * HD + c], o);
        atomicAdd(&ss[c + 0], o.x); atomicAdd(&ss[c + 1], o.y);
        atomicAdd(&ss[c + 2], o.z); atomicAdd(&ss[c + 3], o.w);
        atomicAdd(&sq[c + 0], o.x * o.x); atomicAdd(&sq[c + 1], o.y * o.y);
        atomicAdd(&sq[c + 2], o.z * o.z); atomicAdd(&sq[c + 3], o.w * o.w);
    }
    __syncthreads();
    if (tid < HD) {
        atomicAdd(&d_stats[tid], ss[tid]);
        atomicAdd(&d_stats[HD + tid], sq[tid]);
    }
}

// ---------------- fused FFMA GEMM, 128x128 tile, 8x8 per thread ----------------
// A = relu(bn(t2)) (+h_old) -> written to h; t1h = half(A @ W)
// A stored k-major in smem for float4 compute reads. BK=32, 4 chunks.
#define APAD 132
__global__ void __launch_bounds__(256) k_gemm_fused(const float* __restrict__ W, int n, int res) {
    __shared__ float As[32][APAD];   // k-major: As[k][row], pad 132 (16B-aligned rows kept)
    __shared__ float Ws[32][HD];     // Ws[k][col]
    int row0 = blockIdx.x * 128;
    int tid = threadIdx.x;
    int ty = tid >> 4, tx = tid & 15;          // 16x16 thread grid

    float acc[8][8];
#pragma unroll
    for (int r = 0; r < 8; r++)
#pragma unroll
        for (int c = 0; c < 8; c++) acc[r][c] = 0.f;

    for (int k0 = 0; k0 < HD; k0 += 32) {
        // ---- load A chunk (128 rows x 32 k): BN(+res), write h, store k-major ----
#pragma unroll
        for (int it = 0; it < 4; it++) {
            int l = tid + it * 256;              // 0..1023 float4 slots
            int r = l >> 3, c4 = l & 7;          // row 0..127, float4-col 0..7
            int gr = row0 + r;
            float4 a = make_float4(0.f, 0.f, 0.f, 0.f);
            if (gr < n) {
                int gi = gr * HD + k0 + c4 * 4;
                float4 t2v = __ldcs((const float4*)&d_t2[gi]);
                float4 sc  = *(const float4*)&d_scale[k0 + c4 * 4];
                float4 sh  = *(const float4*)&d_shift[k0 + c4 * 4];
                a.x = fmaxf(t2v.x * sc.x + sh.x, 0.f);
                a.y = fmaxf(t2v.y * sc.y + sh.y, 0.f);
                a.z = fmaxf(t2v.z * sc.z + sh.z, 0.f);
                a.w = fmaxf(t2v.w * sc.w + sh.w, 0.f);
                if (res) {
                    float4 hp = *(const float4*)&d_h[gi];
                    a.x += hp.x; a.y += hp.y; a.z += hp.z; a.w += hp.w;
                }
                *(float4*)&d_h[gi] = a;          // materialize new h
            }
            As[c4 * 4 + 0][r] = a.x;
            As[c4 * 4 + 1][r] = a.y;
            As[c4 * 4 + 2][r] = a.z;
            As[c4 * 4 + 3][r] = a.w;
        }
        // ---- load W chunk (32 k x 128 cols) ----
#pragma unroll
        for (int it = 0; it < 4; it++) {
            int l = tid + it * 256;              // 0..1023 float4 slots
            int r = l >> 5, c4 = l & 31;
            *(float4*)&Ws[r][c4 * 4] = *(const float4*)&W[(k0 + r) * HD + c4 * 4];
        }
        __syncthreads();
        // ---- compute: 64 FFMA per kk per thread ----
#pragma unroll 2
        for (int kk = 0; kk < 32; kk++) {
            float4 a0 = *(const float4*)&As[kk][ty * 8];
            float4 a1 = *(const float4*)&As[kk][ty * 8 + 4];
            float4 b0 = *(const float4*)&Ws[kk][tx * 8];
            float4 b1 = *(const float4*)&Ws[kk][tx * 8 + 4];
            float av[8] = {a0.x, a0.y, a0.z, a0.w, a1.x, a1.y, a1.z, a1.w};
            float bv[8] = {b0.x, b0.y, b0.z, b0.w, b1.x, b1.y, b1.z, b1.w};
#pragma unroll
            for (int r = 0; r < 8; r++)
#pragma unroll
                for (int c = 0; c < 8; c++)
                    acc[r][c] += av[r] * bv[c];
        }
        __syncthreads();
    }

    // ---- epilogue: fp16 t1h, 16B per row-segment ----
#pragma unroll
    for (int r = 0; r < 8; r++) {
        int gr = row0 + ty * 8 + r;
        if (gr < n) {
            union { __half2 h2[4]; uint4 u; } pk;
            pk.h2[0] = __floats2half2_rn(acc[r][0], acc[r][1]);
            pk.h2[1] = __floats2half2_rn(acc[r][2], acc[r][3]);
            pk.h2[2] = __floats2half2_rn(acc[r][4], acc[r][5]);
            pk.h2[3] = __floats2half2_rn(acc[r][6], acc[r][7]);
            *(uint4*)&d_t1h[gr * HD + tx * 8] = pk.u;
        }
    }
}

// ---------------- aggregation (gather-CSR, fp16 source) + fused BN stats ----------------
__global__ void __launch_bounds__(512) k_agg(int n) {
    __shared__ float ss[HD], sq[HD];
    int tid = threadIdx.x;
    if (tid < HD) { ss[tid] = 0.f; sq[tid] = 0.f; }
    __syncthreads();

    const __half2* t1h2 = (const __half2*)d_t1h;
    int node = blockIdx.x * 16 + (tid >> 5);
    int lane = tid & 31;
    if (node < n) {
        int beg = d_rowstart[node], end = d_rowstart[node + 1];
        float dv = d_dinv2[node];

        // self term
        uint2 sraw = *(const uint2*)&t1h2[node * 64 + lane * 2];
        float2 sf0 = __half22float2(*(__half2*)&sraw.x);
        float2 sf1 = __half22float2(*(__half2*)&sraw.y);
        float4 acc = make_float4(sf0.x * dv, sf0.y * dv, sf1.x * dv, sf1.y * dv);

        int j = beg;
        for (; j + 1 < end; j += 2) {
            int   so0 = __ldcs(&d_csr_srco[j]),  so1 = __ldcs(&d_csr_srco[j + 1]);
            float nm0 = __ldcs(&d_csr_norm[j]),  nm1 = __ldcs(&d_csr_norm[j + 1]);
            uint2 r0 = *(const uint2*)&t1h2[so0 + lane * 2];
            uint2 r1 = *(const uint2*)&t1h2[so1 + lane * 2];
            float2 a00 = __half22float2(*(__half2*)&r0.x);
            float2 a01 = __half22float2(*(__half2*)&r0.y);
            float2 a10 = __half22float2(*(__half2*)&r1.x);
            float2 a11 = __half22float2(*(__half2*)&r1.y);
            acc.x += a00.x * nm0 + a10.x * nm1;
            acc.y += a00.y * nm0 + a10.y * nm1;
            acc.z += a01.x * nm0 + a11.x * nm1;
            acc.w += a01.y * nm0 + a11.y * nm1;
        }
        if (j < end) {
            int so = __ldcs(&d_csr_srco[j]); float nm = __ldcs(&d_csr_norm[j]);
            uint2 r0 = *(const uint2*)&t1h2[so + lane * 2];
            float2 a0 = __half22float2(*(__half2*)&r0.x);
            float2 a1 = __half22float2(*(__half2*)&r0.y);
            acc.x += a0.x * nm; acc.y += a0.y * nm;
            acc.z += a1.x * nm; acc.w += a1.y * nm;
        }
        __stcs((float4*)&d_t2[node * HD + lane * 4], acc);

        int c = lane * 4;
        atomicAdd(&ss[c + 0], acc.x); atomicAdd(&ss[c + 1], acc.y);
        atomicAdd(&ss[c + 2], acc.z); atomicAdd(&ss[c + 3], acc.w);
        atomicAdd(&sq[c + 0], acc.x * acc.x); atomicAdd(&sq[c + 1], acc.y * acc.y);
        atomicAdd(&sq[c + 2], acc.z * acc.z); atomicAdd(&sq[c + 3], acc.w * acc.w);
    }
    __syncthreads();
    if (tid < HD) {
        atomicAdd(&d_stats[tid], ss[tid]);
        atomicAdd(&d_stats[HD + tid], sq[tid]);
    }
}

// ---------------- finalize BN params, reset stats ----------------
__global__ void k_finalize(const float* __restrict__ g, const float* __restrict__ beta, int n) {
    int c = threadIdx.x;
    float inv_n = 1.0f / (float)n;
    float mean = d_stats[c] * inv_n;
    float var  = d_stats[HD + c] * inv_n - mean * mean;
    var = fmaxf(var, 0.0f);
    float rs = rsqrtf(var + EPSBN);
    float sc = g[c] * rs;
    d_scale[c] = sc;
    d_shift[c] = beta[c] - mean * sc;
    d_stats[c] = 0.f;
    d_stats[HD + c] = 0.f;
}

// ---------------- final apply (last layer) + fused mean-pool partials ----------------
__global__ void __launch_bounds__(256) k_apply_final(int n) {
    __shared__ float ps[HD];
    int tid = threadIdx.x;
    if (tid < HD) ps[tid] = 0.f;
    __syncthreads();

    int idx = blockIdx.x * blockDim.x + tid;
    if (idx < n * 32) {
        int c = (idx & 31) * 4;
        float4 t  = __ldcs(&((const float4*)d_t2)[idx]);
        float4 sc = *(const float4*)&d_scale[c];
        float4 sh = *(const float4*)&d_shift[c];
        float4 hp = ((const float4*)d_h)[idx];
        float4 o;
        o.x = fmaxf(t.x * sc.x + sh.x, 0.f) + hp.x;
        o.y = fmaxf(t.y * sc.y + sh.y, 0.f) + hp.y;
        o.z = fmaxf(t.z * sc.z + sh.z, 0.f) + hp.z;
        o.w = fmaxf(t.w * sc.w + sh.w, 0.f) + hp.w;
        ((float4*)d_h)[idx] = o;
        atomicAdd(&ps[c + 0], o.x); atomicAdd(&ps[c + 1], o.y);
        atomicAdd(&ps[c + 2], o.z); atomicAdd(&ps[c + 3], o.w);
    }
    __syncthreads();
    if (tid < HD) atomicAdd(&d_pool[tid], ps[tid]);
}

// ---------------- policy head ----------------
__global__ void __launch_bounds__(256) k_policy(const float* __restrict__ pW1,
                                                const float* __restrict__ pb1,
                                                const float* __restrict__ pW2,
                                                const float* __restrict__ pb2,
                                                float* __restrict__ out, int n) {
    int gw = (blockIdx.x * blockDim.x + threadIdx.x) >> 5;
    int lane = threadIdx.x & 31;
    if (gw >= n) return;
    const float* hr = d_h + gw * HD;
    float h0 = hr[lane], h1 = hr[lane + 32], h2 = hr[lane + 64], h3 = hr[lane + 96];
    float acc = 0.f;
#pragma unroll
    for (int k = 0; k < 128; k++) {
        float src = (k < 32) ? h0 : (k < 64) ? h1 : (k < 96) ? h2 : h3;
        float hv = __shfl_sync(0xffffffffu, src, k & 31);
        acc += hv * pW1[k * 32 + lane];
    }
    float u = fmaxf(acc + pb1[lane], 0.f);
    float pv = u * pW2[lane];
#pragma unroll
    for (int off = 16; off; off >>= 1) pv += __shfl_down_sync(0xffffffffu, pv, off);
    if (lane == 0) out[gw] = pv + pb2[0];
}

// ---------------- value head ----------------
__global__ void k_value(const float* __restrict__ vW1, const float* __restrict__ vb1,
                        const float* __restrict__ vW2, const float* __restrict__ vb2,
                        float* __restrict__ out, int n) {
    __shared__ float gm[HD];
    __shared__ float red[64];
    int t = threadIdx.x;
    if (t < HD) gm[t] = d_pool[t] / (float)n;
    __syncthreads();
    if (t < 64) {
        float acc = 0.f;
#pragma unroll 8
        for (int k = 0; k < 128; k++) acc += gm[k] * vW1[k * 64 + t];
        float u = fmaxf(acc + vb1[t], 0.f);
        red[t] = u * vW2[t];
    }
    __syncthreads();
    if (t == 0) {
        float s = 0.f;
        for (int i = 0; i < 64; i++) s += red[i];
        out[n] = tanhf(s + vb2[0]);
    }
}

// ---------------- launcher ----------------
extern "C" void kernel_launch(void* const* d_in, const int* in_sizes, int n_in,
                              void* d_out, int out_size) {
    const float* x  = (const float*)d_in[0];
    const int*   ei = (const int*)d_in[1];     // int32 (JAX x64-disabled)
    // d_in[2] batch: single graph, unused
    const float* in_W    = (const float*)d_in[3];
    // d_in[4] in_b cancels through BN
    const float* in_g    = (const float*)d_in[5];
    const float* in_beta = (const float*)d_in[6];
    const float* conv_W  = (const float*)d_in[7];
    // d_in[8] conv_b cancels through BN
    const float* bn_g    = (const float*)d_in[9];
    const float* bn_beta = (const float*)d_in[10];
    const float* pW1 = (const float*)d_in[11];
    const float* pb1 = (const float*)d_in[12];
    const float* pW2 = (const float*)d_in[13];
    const float* pb2 = (const float*)d_in[14];
    const float* vW1 = (const float*)d_in[15];
    const float* vb1 = (const float*)d_in[16];
    const float* vW2 = (const float*)d_in[17];
    const float* vb2 = (const float*)d_in[18];
    float* out = (float*)d_out;

    int n = in_sizes[0] / 5;
    int e = in_sizes[1] / 2;

    int nb   = (n + 255) / 256;
    int eb   = (e + 255) / 256;
    int nvb  = (n * 32 + 255) / 256;      // one thread per float4 of [N,128]
    int nblk = nb;

    // prep: CSR by dst (parallel scan)
    k_init<<<nb, 256>>>(n);
    k_count<<<eb, 256>>>(ei, e);
    k_dinv<<<nb, 256>>>(n);
    k_scan1<<<nblk, 256>>>(n);
    k_scan2<<<1, 512>>>(nblk, n);
    k_scan3<<<nblk, 256>>>(n);
    k_fill<<<eb, 256>>>(ei, e);

    // input layer (stats fused)
    k_ingemm<<<nvb, 256>>>(x, in_W, n);
    k_finalize<<<1, 128>>>(in_g, in_beta, n);

    // 6 GCN layers: FFMA gemm (8x8 reg tile) applies previous BN+relu(+res); fp16 t1
    for (int l = 0; l < 6; l++) {
        k_gemm_fused<<<(n + 127) / 128, 256>>>(conv_W + (size_t)l * HD * HD, n, l > 0 ? 1 : 0);
        k_agg<<<(n + 15) / 16, 512>>>(n);
        k_finalize<<<1, 128>>>(bn_g + l * HD, bn_beta + l * HD, n);
    }

    // final apply (+pool fusion), heads
    k_apply_final<<<nvb, 256>>>(n);
    k_policy<<<nvb, 256>>>(pW1, pb1, pW2, pb2, out, n);
    k_value<<<1, 128>>>(vW1, vb1, vW2, vb2, out, n);
}

// round 9
// speedup vs baseline: 1.1623x; 1.1623x over previous
#include <cuda_runtime.h>
#include <cuda_fp16.h>

#define HD 128
#define NMAX 100000
#define EMAX 3200000
#define EPSBN 1e-5f

// ---------------- scratch (static device globals; no allocation) ----------------
__device__ __align__(16) float  d_h  [NMAX * HD];    // current node features
__device__ __align__(16) __half d_t1h[NMAX * HD];    // h @ W  (fp16 gather source)
__device__ __align__(16) float  d_t2 [NMAX * HD];    // aggregated
__device__ __align__(16) float  d_dinv [NMAX];       // deg^-1/2
__device__ __align__(16) float  d_dinv2[NMAX];       // deg^-1  (self-loop norm)
__device__ __align__(16) int    d_cnt [NMAX];        // in-degree histogram (excl. self loop)
__device__ __align__(16) int    d_fill[NMAX];        // CSR fill cursors
__device__ __align__(16) int    d_rowstart[NMAX + 4];
__device__ __align__(16) int    d_bsum[512];         // scan block partials
__device__ __align__(16) int    d_boff[512];         // scan block offsets
__device__ __align__(16) int    d_csr_srco[EMAX];    // src * 64 (half2 offset) per CSR slot
__device__ __align__(16) float  d_csr_norm[EMAX];    // edge norm per CSR slot
__device__ __align__(16) float  d_stats[2 * HD];     // [sum, sumsq]
__device__ __align__(16) float  d_scale[HD];
__device__ __align__(16) float  d_shift[HD];
__device__ __align__(16) float  d_pool[HD];

// ---------------- tf32 helpers ----------------
__device__ __forceinline__ unsigned tf32_of(float x) {
    unsigned r;
    asm("cvt.rna.tf32.f32 %0, %1;" : "=r"(r) : "f"(x));
    return r;
}

__device__ __forceinline__ void mma_tf32(float* c, unsigned a0, unsigned a1,
                                         unsigned a2, unsigned a3,
                                         unsigned b0, unsigned b1) {
    asm volatile(
        "mma.sync.aligned.m16n8k8.row.col.f32.tf32.tf32.f32 "
        "{%0,%1,%2,%3}, {%4,%5,%6,%7}, {%8,%9}, {%0,%1,%2,%3};"
        : "+f"(c[0]), "+f"(c[1]), "+f"(c[2]), "+f"(c[3])
        : "r"(a0), "r"(a1), "r"(a2), "r"(a3), "r"(b0), "r"(b1));
}

// ---------------- prep ----------------
__global__ void k_init(int n) {
    int i = blockIdx.x * blockDim.x + threadIdx.x;
    if (i < n) { d_cnt[i] = 0; d_fill[i] = 0; }
    if (i < 2 * HD) d_stats[i] = 0.0f;
    if (i < HD) d_pool[i] = 0.0f;
}

// edge_index is int32 on device (JAX default x64-disabled)
__global__ void k_count(const int* __restrict__ ei, int e) {
    int i = blockIdx.x * blockDim.x + threadIdx.x;
    if (i < e) atomicAdd(&d_cnt[ei[e + i]], 1);   // row 1 = dst
}

__global__ void k_dinv(int n) {
    int i = blockIdx.x * blockDim.x + threadIdx.x;
    if (i < n) {
        float deg = (float)(d_cnt[i] + 1);   // + self loop
        d_dinv[i]  = rsqrtf(deg);
        d_dinv2[i] = 1.0f / deg;
    }
}

// ---- parallel scan: phase 1, per-block reduce ----
__global__ void __launch_bounds__(256) k_scan1(int n) {
    __shared__ int s[256];
    int tid = threadIdx.x;
    int i = blockIdx.x * 256 + tid;
    s[tid] = (i < n) ? d_cnt[i] : 0;
    __syncthreads();
#pragma unroll
    for (int off = 128; off; off >>= 1) {
        if (tid < off) s[tid] += s[tid + off];
        __syncthreads();
    }
    if (tid == 0) d_bsum[blockIdx.x] = s[0];
}

// ---- phase 2: single-block scan of <=512 partials ----
__global__ void __launch_bounds__(512) k_scan2(int nblk, int n) {
    __shared__ int s[512];
    int tid = threadIdx.x;
    int v = (tid < nblk) ? d_bsum[tid] : 0;
    s[tid] = v;
    __syncthreads();
#pragma unroll
    for (int off = 1; off < 512; off <<= 1) {
        int t = (tid >= off) ? s[tid - off] : 0;
        __syncthreads();
        s[tid] += t;
        __syncthreads();
    }
    if (tid < nblk) d_boff[tid] = s[tid] - v;   // exclusive
    if (tid == 511) d_rowstart[n] = s[511];
}

// ---- phase 3: per-block local exclusive scan + offset ----
__global__ void __launch_bounds__(256) k_scan3(int n) {
    __shared__ int s[256];
    int tid = threadIdx.x;
    int i = blockIdx.x * 256 + tid;
    int v = (i < n) ? d_cnt[i] : 0;
    s[tid] = v;
    __syncthreads();
#pragma unroll
    for (int off = 1; off < 256; off <<= 1) {
        int t = (tid >= off) ? s[tid - off] : 0;
        __syncthreads();
        s[tid] += t;
        __syncthreads();
    }
    if (i < n) d_rowstart[i] = d_boff[blockIdx.x] + s[tid] - v;
}

__global__ void k_fill(const int* __restrict__ ei, int e) {
    int i = blockIdx.x * blockDim.x + threadIdx.x;
    if (i < e) {
        int s = ei[i];
        int d = ei[e + i];
        int pos = d_rowstart[d] + atomicAdd(&d_fill[d], 1);
        d_csr_srco[pos] = s * 64;              // half2 offset (64 half2 per row)
        d_csr_norm[pos] = d_dinv[s] * d_dinv[d];
    }
}

// ---------------- input layer: t2 = x @ in_W, fused BN stats ----------------
__global__ void __launch_bounds__(256) k_ingemm(const float* __restrict__ x,
                                                const float* __restrict__ W, int n) {
    __shared__ float ss[HD], sq[HD];
    int tid = threadIdx.x;
    if (tid < HD) { ss[tid] = 0.f; sq[tid] = 0.f; }
    __syncthreads();

    int idx = blockIdx.x * blockDim.x + tid;
    int i = idx >> 5, c4 = idx & 31;
    if (i < n) {
        const float* xr = x + i * 5;
        float x0 = xr[0], x1 = xr[1], x2 = xr[2], x3 = xr[3], x4 = xr[4];
        int c = c4 * 4;
        float4 o;
        o.x = x0*W[0*HD+c+0] + x1*W[1*HD+c+0] + x2*W[2*HD+c+0] + x3*W[3*HD+c+0] + x4*W[4*HD+c+0];
        o.y = x0*W[0*HD+c+1] + x1*W[1*HD+c+1] + x2*W[2*HD+c+1] + x3*W[3*HD+c+1] + x4*W[4*HD+c+1];
        o.z = x0*W[0*HD+c+2] + x1*W[1*HD+c+2] + x2*W[2*HD+c+2] + x3*W[3*HD+c+2] + x4*W[4*HD+c+2];
        o.w = x0*W[0*HD+c+3] + x1*W[1*HD+c+3] + x2*W[2*HD+c+3] + x3*W[3*HD+c+3] + x4*W[4*HD+c+3];
        __stcs((float4*)&d_t2[i * HD + c], o);
        atomicAdd(&ss[c + 0], o.x); atomicAdd(&ss[c + 1], o.y);
        atomicAdd(&ss[c + 2], o.z); atomicAdd(&ss[c + 3], o.w);
        atomicAdd(&sq[c + 0], o.x * o.x); atomicAdd(&sq[c + 1], o.y * o.y);
        atomicAdd(&sq[c + 2], o.z * o.z); atomicAdd(&sq[c + 3], o.w * o.w);
    }
    __syncthreads();
    if (tid < HD) {
        atomicAdd(&d_stats[tid], ss[tid]);
        atomicAdd(&d_stats[HD + tid], sq[tid]);
    }
}

// ---------------- tensor-core GEMM (1x TF32): A = relu(bn(t2))(+h) -> h; t1h = half(A @ W) ----------------
// Tile 128x128, BK=16 chunks, 256 threads = 8 warps (4 m-groups x 2 n-groups).
// Each warp: 32 rows x 64 cols = 2 m-tiles x 8 n-tiles of m16n8k8.
// Fragment layout validated in R6 (passed at 4.7e-5 with the 3x variant).
#define BK 16
__global__ void __launch_bounds__(256) k_gemm_tc(const float* __restrict__ W, int n, int res) {
    __shared__ unsigned Ah[128][BK + 1];   // row-major, pad 1
    __shared__ unsigned Wh[BK][HD + 8];    // k-major, pad 8

    int row0 = blockIdx.x * 128;
    int tid = threadIdx.x;
    int wid = tid >> 5, lane = tid & 31;
    int g = lane >> 2, t = lane & 3;
    int warpm = wid & 3;         // m-offset = warpm*32
    int warpn = wid >> 2;        // n-offset = warpn*64

    float acc[2][8][4];
#pragma unroll
    for (int m = 0; m < 2; m++)
#pragma unroll
        for (int nt = 0; nt < 8; nt++)
#pragma unroll
            for (int q = 0; q < 4; q++) acc[m][nt][q] = 0.f;

    for (int k0 = 0; k0 < HD; k0 += BK) {
        // ---- load A chunk: BN(+res) transform, write h, cvt tf32 ----
#pragma unroll
        for (int it = 0; it < 2; it++) {
            int l = tid + it * 256;          // 512 float4 = 128 rows x 4
            int r = l >> 2, c4 = l & 3;
            int gr = row0 + r;
            float4 a = make_float4(0.f, 0.f, 0.f, 0.f);
            if (gr < n) {
                int gi = gr * HD + k0 + c4 * 4;
                float4 t2v = __ldcs((const float4*)&d_t2[gi]);
                float4 sc  = *(const float4*)&d_scale[k0 + c4 * 4];
                float4 sh  = *(const float4*)&d_shift[k0 + c4 * 4];
                a.x = fmaxf(t2v.x * sc.x + sh.x, 0.f);
                a.y = fmaxf(t2v.y * sc.y + sh.y, 0.f);
                a.z = fmaxf(t2v.z * sc.z + sh.z, 0.f);
                a.w = fmaxf(t2v.w * sc.w + sh.w, 0.f);
                if (res) {
                    float4 hp = *(const float4*)&d_h[gi];
                    a.x += hp.x; a.y += hp.y; a.z += hp.z; a.w += hp.w;
                }
                *(float4*)&d_h[gi] = a;      // materialize new h
            }
            Ah[r][c4 * 4 + 0] = tf32_of(a.x);
            Ah[r][c4 * 4 + 1] = tf32_of(a.y);
            Ah[r][c4 * 4 + 2] = tf32_of(a.z);
            Ah[r][c4 * 4 + 3] = tf32_of(a.w);
        }
        // ---- load W chunk (k-major) cvt tf32 ----
#pragma unroll
        for (int it = 0; it < 2; it++) {
            int l = tid + it * 256;          // 512 float4 = 16 rows x 32
            int r = l >> 5, c4 = l & 31;
            float4 w = *(const float4*)&W[(k0 + r) * HD + c4 * 4];
            Wh[r][c4 * 4 + 0] = tf32_of(w.x);
            Wh[r][c4 * 4 + 1] = tf32_of(w.y);
            Wh[r][c4 * 4 + 2] = tf32_of(w.z);
            Wh[r][c4 * 4 + 3] = tf32_of(w.w);
        }
        __syncthreads();

#pragma unroll
        for (int kk = 0; kk < BK / 8; kk++) {
            int kb = kk * 8;
            unsigned ah[2][4];
#pragma unroll
            for (int m = 0; m < 2; m++) {
                int rA = warpm * 32 + m * 16 + g;
                ah[m][0] = Ah[rA    ][kb + t];
                ah[m][1] = Ah[rA + 8][kb + t];
                ah[m][2] = Ah[rA    ][kb + t + 4];
                ah[m][3] = Ah[rA + 8][kb + t + 4];
            }
#pragma unroll
            for (int nt = 0; nt < 8; nt++) {
                int cB = warpn * 64 + nt * 8 + g;
                unsigned bh0 = Wh[kb + t    ][cB];
                unsigned bh1 = Wh[kb + t + 4][cB];
#pragma unroll
                for (int m = 0; m < 2; m++)
                    mma_tf32(acc[m][nt], ah[m][0], ah[m][1], ah[m][2], ah[m][3], bh0, bh1);
            }
        }
        __syncthreads();
    }

    // ---- epilogue: write fp16 t1h ----
    // c0,c1 -> (row g, cols 2t,2t+1); c2,c3 -> (row g+8, same cols)
#pragma unroll
    for (int m = 0; m < 2; m++) {
        int r0 = row0 + warpm * 32 + m * 16 + g;
#pragma unroll
        for (int nt = 0; nt < 8; nt++) {
            int col = warpn * 64 + nt * 8 + t * 2;
            if (r0 < n) {
                __half2 p = __floats2half2_rn(acc[m][nt][0], acc[m][nt][1]);
                *(unsigned*)&d_t1h[r0 * HD + col] = *(unsigned*)&p;
            }
            if (r0 + 8 < n) {
                __half2 p = __floats2half2_rn(acc[m][nt][2], acc[m][nt][3]);
                *(unsigned*)&d_t1h[(r0 + 8) * HD + col] = *(unsigned*)&p;
            }
        }
    }
}

// ---------------- aggregation (gather-CSR, fp16 source) + fused BN stats ----------------
__global__ void __launch_bounds__(512) k_agg(int n) {
    __shared__ float ss[HD], sq[HD];
    int tid = threadIdx.x;
    if (tid < HD) { ss[tid] = 0.f; sq[tid] = 0.f; }
    __syncthreads();

    const __half2* t1h2 = (const __half2*)d_t1h;
    int node = blockIdx.x * 16 + (tid >> 5);
    int lane = tid & 31;
    if (node < n) {
        int beg = d_rowstart[node], end = d_rowstart[node + 1];
        float dv = d_dinv2[node];

        // self term
        uint2 sraw = *(const uint2*)&t1h2[node * 64 + lane * 2];
        float2 sf0 = __half22float2(*(__half2*)&sraw.x);
        float2 sf1 = __half22float2(*(__half2*)&sraw.y);
        float4 acc = make_float4(sf0.x * dv, sf0.y * dv, sf1.x * dv, sf1.y * dv);

        int j = beg;
        for (; j + 1 < end; j += 2) {
            int   so0 = __ldcs(&d_csr_srco[j]),  so1 = __ldcs(&d_csr_srco[j + 1]);
            float nm0 = __ldcs(&d_csr_norm[j]),  nm1 = __ldcs(&d_csr_norm[j + 1]);
            uint2 r0 = *(const uint2*)&t1h2[so0 + lane * 2];
            uint2 r1 = *(const uint2*)&t1h2[so1 + lane * 2];
            float2 a00 = __half22float2(*(__half2*)&r0.x);
            float2 a01 = __half22float2(*(__half2*)&r0.y);
            float2 a10 = __half22float2(*(__half2*)&r1.x);
            float2 a11 = __half22float2(*(__half2*)&r1.y);
            acc.x += a00.x * nm0 + a10.x * nm1;
            acc.y += a00.y * nm0 + a10.y * nm1;
            acc.z += a01.x * nm0 + a11.x * nm1;
            acc.w += a01.y * nm0 + a11.y * nm1;
        }
        if (j < end) {
            int so = __ldcs(&d_csr_srco[j]); float nm = __ldcs(&d_csr_norm[j]);
            uint2 r0 = *(const uint2*)&t1h2[so + lane * 2];
            float2 a0 = __half22float2(*(__half2*)&r0.x);
            float2 a1 = __half22float2(*(__half2*)&r0.y);
            acc.x += a0.x * nm; acc.y += a0.y * nm;
            acc.z += a1.x * nm; acc.w += a1.y * nm;
        }
        __stcs((float4*)&d_t2[node * HD + lane * 4], acc);

        int c = lane * 4;
        atomicAdd(&ss[c + 0], acc.x); atomicAdd(&ss[c + 1], acc.y);
        atomicAdd(&ss[c + 2], acc.z); atomicAdd(&ss[c + 3], acc.w);
        atomicAdd(&sq[c + 0], acc.x * acc.x); atomicAdd(&sq[c + 1], acc.y * acc.y);
        atomicAdd(&sq[c + 2], acc.z * acc.z); atomicAdd(&sq[c + 3], acc.w * acc.w);
    }
    __syncthreads();
    if (tid < HD) {
        atomicAdd(&d_stats[tid], ss[tid]);
        atomicAdd(&d_stats[HD + tid], sq[tid]);
    }
}

// ---------------- finalize BN params, reset stats ----------------
__global__ void k_finalize(const float* __restrict__ g, const float* __restrict__ beta, int n) {
    int c = threadIdx.x;
    float inv_n = 1.0f / (float)n;
    float mean = d_stats[c] * inv_n;
    float var  = d_stats[HD + c] * inv_n - mean * mean;
    var = fmaxf(var, 0.0f);
    float rs = rsqrtf(var + EPSBN);
    float sc = g[c] * rs;
    d_scale[c] = sc;
    d_shift[c] = beta[c] - mean * sc;
    d_stats[c] = 0.f;
    d_stats[HD + c] = 0.f;
}

// ---------------- final apply (last layer) + fused mean-pool partials ----------------
__global__ void __launch_bounds__(256) k_apply_final(int n) {
    __shared__ float ps[HD];
    int tid = threadIdx.x;
    if (tid < HD) ps[tid] = 0.f;
    __syncthreads();

    int idx = blockIdx.x * blockDim.x + tid;
    if (idx < n * 32) {
        int c = (idx & 31) * 4;
        float4 t  = __ldcs(&((const float4*)d_t2)[idx]);
        float4 sc = *(const float4*)&d_scale[c];
        float4 sh = *(const float4*)&d_shift[c];
        float4 hp = ((const float4*)d_h)[idx];
        float4 o;
        o.x = fmaxf(t.x * sc.x + sh.x, 0.f) + hp.x;
        o.y = fmaxf(t.y * sc.y + sh.y, 0.f) + hp.y;
        o.z = fmaxf(t.z * sc.z + sh.z, 0.f) + hp.z;
        o.w = fmaxf(t.w * sc.w + sh.w, 0.f) + hp.w;
        ((float4*)d_h)[idx] = o;
        atomicAdd(&ps[c + 0], o.x); atomicAdd(&ps[c + 1], o.y);
        atomicAdd(&ps[c + 2], o.z); atomicAdd(&ps[c + 3], o.w);
    }
    __syncthreads();
    if (tid < HD) atomicAdd(&d_pool[tid], ps[tid]);
}

// ---------------- policy head ----------------
__global__ void __launch_bounds__(256) k_policy(const float* __restrict__ pW1,
                                                const float* __restrict__ pb1,
                                                const float* __restrict__ pW2,
                                                const float* __restrict__ pb2,
                                                float* __restrict__ out, int n) {
    int gw = (blockIdx.x * blockDim.x + threadIdx.x) >> 5;
    int lane = threadIdx.x & 31;
    if (gw >= n) return;
    const float* hr = d_h + gw * HD;
    float h0 = hr[lane], h1 = hr[lane + 32], h2 = hr[lane + 64], h3 = hr[lane + 96];
    float acc = 0.f;
#pragma unroll
    for (int k = 0; k < 128; k++) {
        float src = (k < 32) ? h0 : (k < 64) ? h1 : (k < 96) ? h2 : h3;
        float hv = __shfl_sync(0xffffffffu, src, k & 31);
        acc += hv * pW1[k * 32 + lane];
    }
    float u = fmaxf(acc + pb1[lane], 0.f);
    float pv = u * pW2[lane];
#pragma unroll
    for (int off = 16; off; off >>= 1) pv += __shfl_down_sync(0xffffffffu, pv, off);
    if (lane == 0) out[gw] = pv + pb2[0];
}

// ---------------- value head ----------------
__global__ void k_value(const float* __restrict__ vW1, const float* __restrict__ vb1,
                        const float* __restrict__ vW2, const float* __restrict__ vb2,
                        float* __restrict__ out, int n) {
    __shared__ float gm[HD];
    __shared__ float red[64];
    int t = threadIdx.x;
    if (t < HD) gm[t] = d_pool[t] / (float)n;
    __syncthreads();
    if (t < 64) {
        float acc = 0.f;
#pragma unroll 8
        for (int k = 0; k < 128; k++) acc += gm[k] * vW1[k * 64 + t];
        float u = fmaxf(acc + vb1[t], 0.f);
        red[t] = u * vW2[t];
    }
    __syncthreads();
    if (t == 0) {
        float s = 0.f;
        for (int i = 0; i < 64; i++) s += red[i];
        out[n] = tanhf(s + vb2[0]);
    }
}

// ---------------- launcher ----------------
extern "C" void kernel_launch(void* const* d_in, const int* in_sizes, int n_in,
                              void* d_out, int out_size) {
    const float* x  = (const float*)d_in[0];
    const int*   ei = (const int*)d_in[1];     // int32 (JAX x64-disabled)
    // d_in[2] batch: single graph, unused
    const float* in_W    = (const float*)d_in[3];
    // d_in[4] in_b cancels through BN
    const float* in_g    = (const float*)d_in[5];
    const float* in_beta = (const float*)d_in[6];
    const float* conv_W  = (const float*)d_in[7];
    // d_in[8] conv_b cancels through BN
    const float* bn_g    = (const float*)d_in[9];
    const float* bn_beta = (const float*)d_in[10];
    const float* pW1 = (const float*)d_in[11];
    const float* pb1 = (const float*)d_in[12];
    const float* pW2 = (const float*)d_in[13];
    const float* pb2 = (const float*)d_in[14];
    const float* vW1 = (const float*)d_in[15];
    const float* vb1 = (const float*)d_in[16];
    const float* vW2 = (const float*)d_in[17];
    const float* vb2 = (const float*)d_in[18];
    float* out = (float*)d_out;

    int n = in_sizes[0] / 5;
    int e = in_sizes[1] / 2;

    int nb   = (n + 255) / 256;
    int eb   = (e + 255) / 256;
    int nvb  = (n * 32 + 255) / 256;      // one thread per float4 of [N,128]
    int nblk = nb;

    // prep: CSR by dst (parallel scan)
    k_init<<<nb, 256>>>(n);
    k_count<<<eb, 256>>>(ei, e);
    k_dinv<<<nb, 256>>>(n);
    k_scan1<<<nblk, 256>>>(n);
    k_scan2<<<1, 512>>>(nblk, n);
    k_scan3<<<nblk, 256>>>(n);
    k_fill<<<eb, 256>>>(ei, e);

    // input layer (stats fused)
    k_ingemm<<<nvb, 256>>>(x, in_W, n);
    k_finalize<<<1, 128>>>(in_g, in_beta, n);

    // 6 GCN layers: 1x tf32 tensor-core gemm applies previous BN+relu(+res); fp16 t1
    for (int l = 0; l < 6; l++) {
        k_gemm_tc<<<(n + 127) / 128, 256>>>(conv_W + (size_t)l * HD * HD, n, l > 0 ? 1 : 0);
        k_agg<<<(n + 15) / 16, 512>>>(n);
        k_finalize<<<1, 128>>>(bn_g + l * HD, bn_beta + l * HD, n);
    }

    // final apply (+pool fusion), heads
    k_apply_final<<<nvb, 256>>>(n);
    k_policy<<<nvb, 256>>>(pW1, pb1, pW2, pb2, out, n);
    k_value<<<1, 128>>>(vW1, vb1, vW2, vb2, out, n);
}

// round 11
// speedup vs baseline: 1.1664x; 1.0036x over previous
#include <cuda_runtime.h>
#include <cuda_fp16.h>

#define HD 128
#define NMAX 100000
#define EMAX 3200000
#define EPSBN 1e-5f

// ---------------- scratch (static device globals; no allocation) ----------------
__device__ __align__(16) float  d_h  [NMAX * HD];    // current node features
__device__ __align__(16) __half d_t1h[NMAX * HD];    // h @ W  (fp16 gather source)
__device__ __align__(16) float  d_t2 [NMAX * HD];    // aggregated
__device__ __align__(16) float  d_dinv [NMAX];       // deg^-1/2
__device__ __align__(16) float  d_dinv2[NMAX];       // deg^-1  (self-loop norm)
__device__ __align__(16) int    d_cnt [NMAX];        // in-degree histogram (excl. self loop)
__device__ __align__(16) int    d_fill[NMAX];        // CSR fill cursors
__device__ __align__(16) int    d_rowstart[NMAX + 4];
__device__ __align__(16) int    d_bsum[512];         // scan block partials
__device__ __align__(16) int    d_boff[512];         // scan block offsets
__device__ __align__(16) int    d_csr_srco[EMAX];    // src * 64 (half2 offset) per CSR slot
__device__ __align__(16) float  d_csr_norm[EMAX];    // edge norm per CSR slot
__device__ __align__(16) float  d_stats[2 * HD];     // [sum, sumsq]
__device__ __align__(16) float  d_scale[HD];
__device__ __align__(16) float  d_shift[HD];
__device__ __align__(16) float  d_pool[HD];
__device__ int d_done;                               // last-block counter

// ---------------- tf32 helpers ----------------
__device__ __forceinline__ unsigned tf32_of(float x) {
    unsigned r;
    asm("cvt.rna.tf32.f32 %0, %1;" : "=r"(r) : "f"(x));
    return r;
}

__device__ __forceinline__ void mma_tf32(float* c, unsigned a0, unsigned a1,
                                         unsigned a2, unsigned a3,
                                         unsigned b0, unsigned b1) {
    asm volatile(
        "mma.sync.aligned.m16n8k8.row.col.f32.tf32.tf32.f32 "
        "{%0,%1,%2,%3}, {%4,%5,%6,%7}, {%8,%9}, {%0,%1,%2,%3};"
        : "+f"(c[0]), "+f"(c[1]), "+f"(c[2]), "+f"(c[3])
        : "r"(a0), "r"(a1), "r"(a2), "r"(a3), "r"(b0), "r"(b1));
}

// ---------------- fused BN finalize (last-block pattern) ----------------
__device__ __forceinline__ void finalize_bn(const float* __restrict__ g,
                                            const float* __restrict__ beta,
                                            int n, int tid, int nblocks) {
    __shared__ int slast;
    __threadfence();
    __syncthreads();
    if (tid == 0) slast = (atomicAdd(&d_done, 1) == nblocks - 1) ? 1 : 0;
    __syncthreads();
    if (slast) {
        if (tid < HD) {
            float inv_n = 1.0f / (float)n;
            float mean = __ldcg(&d_stats[tid]) * inv_n;
            float var  = __ldcg(&d_stats[HD + tid]) * inv_n - mean * mean;
            var = fmaxf(var, 0.0f);
            float rs = rsqrtf(var + EPSBN);
            float sc = g[tid] * rs;
            d_scale[tid] = sc;
            d_shift[tid] = beta[tid] - mean * sc;
            d_stats[tid] = 0.f;
            d_stats[HD + tid] = 0.f;
        }
        if (tid == 0) d_done = 0;
    }
}

// ---------------- prep ----------------
__global__ void k_init(int n) {
    int i = blockIdx.x * blockDim.x + threadIdx.x;
    if (i < n) { d_cnt[i] = 0; d_fill[i] = 0; }
    if (i < 2 * HD) d_stats[i] = 0.0f;
    if (i < HD) d_pool[i] = 0.0f;
    if (i == 0) d_done = 0;
}

// edge_index is int32 on device (JAX default x64-disabled)
__global__ void k_count(const int* __restrict__ ei, int e) {
    int i = blockIdx.x * blockDim.x + threadIdx.x;
    if (i < e) atomicAdd(&d_cnt[ei[e + i]], 1);   // row 1 = dst
}

__global__ void k_dinv(int n) {
    int i = blockIdx.x * blockDim.x + threadIdx.x;
    if (i < n) {
        float deg = (float)(d_cnt[i] + 1);   // + self loop
        d_dinv[i]  = rsqrtf(deg);
        d_dinv2[i] = 1.0f / deg;
    }
}

// ---- parallel scan: phase 1, per-block reduce ----
__global__ void __launch_bounds__(256) k_scan1(int n) {
    __shared__ int s[256];
    int tid = threadIdx.x;
    int i = blockIdx.x * 256 + tid;
    s[tid] = (i < n) ? d_cnt[i] : 0;
    __syncthreads();
#pragma unroll
    for (int off = 128; off; off >>= 1) {
        if (tid < off) s[tid] += s[tid + off];
        __syncthreads();
    }
    if (tid == 0) d_bsum[blockIdx.x] = s[0];
}

// ---- phase 2: single-block scan of <=512 partials ----
__global__ void __launch_bounds__(512) k_scan2(int nblk, int n) {
    __shared__ int s[512];
    int tid = threadIdx.x;
    int v = (tid < nblk) ? d_bsum[tid] : 0;
    s[tid] = v;
    __syncthreads();
#pragma unroll
    for (int off = 1; off < 512; off <<= 1) {
        int t = (tid >= off) ? s[tid - off] : 0;
        __syncthreads();
        s[tid] += t;
        __syncthreads();
    }
    if (tid < nblk) d_boff[tid] = s[tid] - v;   // exclusive
    if (tid == 511) d_rowstart[n] = s[511];
}

// ---- phase 3: per-block local exclusive scan + offset ----
__global__ void __launch_bounds__(256) k_scan3(int n) {
    __shared__ int s[256];
    int tid = threadIdx.x;
    int i = blockIdx.x * 256 + tid;
    int v = (i < n) ? d_cnt[i] : 0;
    s[tid] = v;
    __syncthreads();
#pragma unroll
    for (int off = 1; off < 256; off <<= 1) {
        int t = (tid >= off) ? s[tid - off] : 0;
        __syncthreads();
        s[tid] += t;
        __syncthreads();
    }
    if (i < n) d_rowstart[i] = d_boff[blockIdx.x] + s[tid] - v;
}

__global__ void k_fill(const int* __restrict__ ei, int e) {
    int i = blockIdx.x * blockDim.x + threadIdx.x;
    if (i < e) {
        int s = ei[i];
        int d = ei[e + i];
        int pos = d_rowstart[d] + atomicAdd(&d_fill[d], 1);
        d_csr_srco[pos] = s * 64;              // half2 offset (64 half2 per row)
        d_csr_norm[pos] = d_dinv[s] * d_dinv[d];
    }
}

// ---------------- input layer: t2 = x @ in_W, fused BN stats + finalize ----------------
__global__ void __launch_bounds__(256) k_ingemm(const float* __restrict__ x,
                                                const float* __restrict__ W,
                                                const float* __restrict__ g,
                                                const float* __restrict__ beta, int n) {
    __shared__ float ss[HD], sq[HD];
    int tid = threadIdx.x;
    if (tid < HD) { ss[tid] = 0.f; sq[tid] = 0.f; }
    __syncthreads();

    int idx = blockIdx.x * blockDim.x + tid;
    int i = idx >> 5, c4 = idx & 31;
    if (i < n) {
        const float* xr = x + i * 5;
        float x0 = xr[0], x1 = xr[1], x2 = xr[2], x3 = xr[3], x4 = xr[4];
        int c = c4 * 4;
        float4 o;
        o.x = x0*W[0*HD+c+0] + x1*W[1*HD+c+0] + x2*W[2*HD+c+0] + x3*W[3*HD+c+0] + x4*W[4*HD+c+0];
        o.y = x0*W[0*HD+c+1] + x1*W[1*HD+c+1] + x2*W[2*HD+c+1] + x3*W[3*HD+c+1] + x4*W[4*HD+c+1];
        o.z = x0*W[0*HD+c+2] + x1*W[1*HD+c+2] + x2*W[2*HD+c+2] + x3*W[3*HD+c+2] + x4*W[4*HD+c+2];
        o.w = x0*W[0*HD+c+3] + x1*W[1*HD+c+3] + x2*W[2*HD+c+3] + x3*W[3*HD+c+3] + x4*W[4*HD+c+3];
        __stcs((float4*)&d_t2[i * HD + c], o);
        atomicAdd(&ss[c + 0], o.x); atomicAdd(&ss[c + 1], o.y);
        atomicAdd(&ss[c + 2], o.z); atomicAdd(&ss[c + 3], o.w);
        atomicAdd(&sq[c + 0], o.x * o.x); atomicAdd(&sq[c + 1], o.y * o.y);
        atomicAdd(&sq[c + 2], o.z * o.z); atomicAdd(&sq[c + 3], o.w * o.w);
    }
    __syncthreads();
    if (tid < HD) {
        atomicAdd(&d_stats[tid], ss[tid]);
        atomicAdd(&d_stats[HD + tid], sq[tid]);
    }
    finalize_bn(g, beta, n, tid, gridDim.x);
}

// ---------------- tensor-core GEMM (1x TF32), whole-A-tile, double-buffered W ----------------
// A = relu(bn(t2))(+h) -> h (streaming); t1h = half(A @ W).
// Dynamic smem: Ah[128][132] tf32 + Whb[2][16][136] tf32 = 84,992 B. 2 blocks/SM.
#define BK 16
#define GEMM_SMEM ((128 * 132 + 2 * 16 * 136) * 4)
__global__ void __launch_bounds__(256, 2) k_gemm_tc(const float* __restrict__ W, int n, int res) {
    extern __shared__ unsigned smem_u[];
    unsigned* Ah  = smem_u;                  // [128][132]
    unsigned* Whb = smem_u + 128 * 132;      // [2][16][136]

    int row0 = blockIdx.x * 128;
    int tid = threadIdx.x;
    int wid = tid >> 5, lane = tid & 31;
    int g = lane >> 2, t = lane & 3;
    int warpm = wid & 3;         // m-offset = warpm*32
    int warpn = wid >> 2;        // n-offset = warpn*64

    // ---- Phase 1: load WHOLE 128x128 A tile (4096 float4 = 16 iters) ----
#pragma unroll
    for (int it = 0; it < 16; it++) {
        int l = tid + it * 256;              // 0..4095 float4 slots
        int r = l >> 5, c4 = l & 31;         // row 0..127, float4-col 0..31
        int gr = row0 + r;
        float4 a = make_float4(0.f, 0.f, 0.f, 0.f);
        if (gr < n) {
            int gi = gr * HD + c4 * 4;
            float4 t2v = __ldcs((const float4*)&d_t2[gi]);
            float4 sc  = *(const float4*)&d_scale[c4 * 4];
            float4 sh  = *(const float4*)&d_shift[c4 * 4];
            a.x = fmaxf(t2v.x * sc.x + sh.x, 0.f);
            a.y = fmaxf(t2v.y * sc.y + sh.y, 0.f);
            a.z = fmaxf(t2v.z * sc.z + sh.z, 0.f);
            a.w = fmaxf(t2v.w * sc.w + sh.w, 0.f);
            if (res) {
                float4 hp = __ldcs((const float4*)&d_h[gi]);
                a.x += hp.x; a.y += hp.y; a.z += hp.z; a.w += hp.w;
            }
            __stcs((float4*)&d_h[gi], a);    // materialize new h (streaming)
        }
        unsigned* arow = Ah + r * 132 + c4 * 4;
        arow[0] = tf32_of(a.x);
        arow[1] = tf32_of(a.y);
        arow[2] = tf32_of(a.z);
        arow[3] = tf32_of(a.w);
    }
    // ---- prefetch W chunk 0 into buffer 0 ----
#pragma unroll
    for (int it = 0; it < 2; it++) {
        int l = tid + it * 256;
        int r = l >> 5, c4 = l & 31;
        float4 w = *(const float4*)&W[r * HD + c4 * 4];
        unsigned* wrow = Whb + r * 136 + c4 * 4;
        wrow[0] = tf32_of(w.x); wrow[1] = tf32_of(w.y);
        wrow[2] = tf32_of(w.z); wrow[3] = tf32_of(w.w);
    }
    __syncthreads();

    float acc[2][8][4];
#pragma unroll
    for (int m = 0; m < 2; m++)
#pragma unroll
        for (int nt = 0; nt < 8; nt++)
#pragma unroll
            for (int q = 0; q < 4; q++) acc[m][nt][q] = 0.f;

    for (int c = 0; c < 8; c++) {
        // prefetch next W chunk into the other buffer (overlaps with mma below)
        if (c + 1 < 8) {
            int k0n = (c + 1) * BK;
            unsigned* wb = Whb + ((c + 1) & 1) * 16 * 136;
#pragma unroll
            for (int it = 0; it < 2; it++) {
                int l = tid + it * 256;
                int r = l >> 5, c4 = l & 31;
                float4 w = *(const float4*)&W[(k0n + r) * HD + c4 * 4];
                unsigned* wrow = wb + r * 136 + c4 * 4;
                wrow[0] = tf32_of(w.x); wrow[1] = tf32_of(w.y);
                wrow[2] = tf32_of(w.z); wrow[3] = tf32_of(w.w);
            }
        }
        int k0 = c * BK;
        unsigned* Wh = Whb + (c & 1) * 16 * 136;
#pragma unroll
        for (int kk = 0; kk < 2; kk++) {
            int kb = kk * 8;
            unsigned ah[2][4];
#pragma unroll
            for (int m = 0; m < 2; m++) {
                int rA = warpm * 32 + m * 16 + g;
                ah[m][0] = Ah[rA * 132 + k0 + kb + t];
                ah[m][1] = Ah[(rA + 8) * 132 + k0 + kb + t];
                ah[m][2] = Ah[rA * 132 + k0 + kb + t + 4];
                ah[m][3] = Ah[(rA + 8) * 132 + k0 + kb + t + 4];
            }
#pragma unroll
            for (int nt = 0; nt < 8; nt++) {
                int cB = warpn * 64 + nt * 8 + g;
                unsigned bh0 = Wh[(kb + t) * 136 + cB];
                unsigned bh1 = Wh[(kb + t + 4) * 136 + cB];
#pragma unroll
                for (int m = 0; m < 2; m++)
                    mma_tf32(acc[m][nt], ah[m][0], ah[m][1], ah[m][2], ah[m][3], bh0, bh1);
            }
        }
        __syncthreads();
    }

    // ---- epilogue: write fp16 t1h (L2-resident for agg gathers) ----
#pragma unroll
    for (int m = 0; m < 2; m++) {
        int r0 = row0 + warpm * 32 + m * 16 + g;
#pragma unroll
        for (int nt = 0; nt < 8; nt++) {
            int col = warpn * 64 + nt * 8 + t * 2;
            if (r0 < n) {
                __half2 p = __floats2half2_rn(acc[m][nt][0], acc[m][nt][1]);
                *(unsigned*)&d_t1h[r0 * HD + col] = *(unsigned*)&p;
            }
            if (r0 + 8 < n) {
                __half2 p = __floats2half2_rn(acc[m][nt][2], acc[m][nt][3]);
                *(unsigned*)&d_t1h[(r0 + 8) * HD + col] = *(unsigned*)&p;
            }
        }
    }
}

// ---------------- aggregation (gather-CSR, fp16) + fused BN stats + finalize ----------------
__global__ void __launch_bounds__(512) k_agg(const float* __restrict__ g_,
                                             const float* __restrict__ beta_, int n) {
    __shared__ float ss[HD], sq[HD];
    int tid = threadIdx.x;
    if (tid < HD) { ss[tid] = 0.f; sq[tid] = 0.f; }
    __syncthreads();

    const __half2* t1h2 = (const __half2*)d_t1h;
    int node = blockIdx.x * 16 + (tid >> 5);
    int lane = tid & 31;
    if (node < n) {
        int beg = d_rowstart[node], end = d_rowstart[node + 1];
        float dv = d_dinv2[node];

        // self term
        uint2 sraw = *(const uint2*)&t1h2[node * 64 + lane * 2];
        float2 sf0 = __half22float2(*(__half2*)&sraw.x);
        float2 sf1 = __half22float2(*(__half2*)&sraw.y);
        float4 acc = make_float4(sf0.x * dv, sf0.y * dv, sf1.x * dv, sf1.y * dv);

        int j = beg;
        for (; j + 1 < end; j += 2) {
            int   so0 = __ldcs(&d_csr_srco[j]),  so1 = __ldcs(&d_csr_srco[j + 1]);
            float nm0 = __ldcs(&d_csr_norm[j]),  nm1 = __ldcs(&d_csr_norm[j + 1]);
            uint2 r0 = *(const uint2*)&t1h2[so0 + lane * 2];
            uint2 r1 = *(const uint2*)&t1h2[so1 + lane * 2];
            float2 a00 = __half22float2(*(__half2*)&r0.x);
            float2 a01 = __half22float2(*(__half2*)&r0.y);
            float2 a10 = __half22float2(*(__half2*)&r1.x);
            float2 a11 = __half22float2(*(__half2*)&r1.y);
            acc.x += a00.x * nm0 + a10.x * nm1;
            acc.y += a00.y * nm0 + a10.y * nm1;
            acc.z += a01.x * nm0 + a11.x * nm1;
            acc.w += a01.y * nm0 + a11.y * nm1;
        }
        if (j < end) {
            int so = __ldcs(&d_csr_srco[j]); float nm = __ldcs(&d_csr_norm[j]);
            uint2 r0 = *(const uint2*)&t1h2[so + lane * 2];
            float2 a0 = __half22float2(*(__half2*)&r0.x);
            float2 a1 = __half22float2(*(__half2*)&r0.y);
            acc.x += a0.x * nm; acc.y += a0.y * nm;
            acc.z += a1.x * nm; acc.w += a1.y * nm;
        }
        __stcs((float4*)&d_t2[node * HD + lane * 4], acc);

        int c = lane * 4;
        atomicAdd(&ss[c + 0], acc.x); atomicAdd(&ss[c + 1], acc.y);
        atomicAdd(&ss[c + 2], acc.z); atomicAdd(&ss[c + 3], acc.w);
        atomicAdd(&sq[c + 0], acc.x * acc.x); atomicAdd(&sq[c + 1], acc.y * acc.y);
        atomicAdd(&sq[c + 2], acc.z * acc.z); atomicAdd(&sq[c + 3], acc.w * acc.w);
    }
    __syncthreads();
    if (tid < HD) {
        atomicAdd(&d_stats[tid], ss[tid]);
        atomicAdd(&d_stats[HD + tid], sq[tid]);
    }
    finalize_bn(g_, beta_, n, tid, gridDim.x);
}

// ---------------- final apply (last layer) + fused mean-pool partials ----------------
__global__ void __launch_bounds__(256) k_apply_final(int n) {
    __shared__ float ps[HD];
    int tid = threadIdx.x;
    if (tid < HD) ps[tid] = 0.f;
    __syncthreads();

    int idx = blockIdx.x * blockDim.x + tid;
    if (idx < n * 32) {
        int c = (idx & 31) * 4;
        float4 t  = __ldcs(&((const float4*)d_t2)[idx]);
        float4 sc = *(const float4*)&d_scale[c];
        float4 sh = *(const float4*)&d_shift[c];
        float4 hp = ((const float4*)d_h)[idx];
        float4 o;
        o.x = fmaxf(t.x * sc.x + sh.x, 0.f) + hp.x;
        o.y = fmaxf(t.y * sc.y + sh.y, 0.f) + hp.y;
        o.z = fmaxf(t.z * sc.z + sh.z, 0.f) + hp.z;
        o.w = fmaxf(t.w * sc.w + sh.w, 0.f) + hp.w;
        ((float4*)d_h)[idx] = o;
        atomicAdd(&ps[c + 0], o.x); atomicAdd(&ps[c + 1], o.y);
        atomicAdd(&ps[c + 2], o.z); atomicAdd(&ps[c + 3], o.w);
    }
    __syncthreads();
    if (tid < HD) atomicAdd(&d_pool[tid], ps[tid]);
}

// ---------------- policy head ----------------
__global__ void __launch_bounds__(256) k_policy(const float* __restrict__ pW1,
                                                const float* __restrict__ pb1,
                                                const float* __restrict__ pW2,
                                                const float* __restrict__ pb2,
                                                float* __restrict__ out, int n) {
    int gw = (blockIdx.x * blockDim.x + threadIdx.x) >> 5;
    int lane = threadIdx.x & 31;
    if (gw >= n) return;
    const float* hr = d_h + gw * HD;
    float h0 = hr[lane], h1 = hr[lane + 32], h2 = hr[lane + 64], h3 = hr[lane + 96];
    float acc = 0.f;
#pragma unroll
    for (int k = 0; k < 128; k++) {
        float src = (k < 32) ? h0 : (k < 64) ? h1 : (k < 96) ? h2 : h3;
        float hv = __shfl_sync(0xffffffffu, src, k & 31);
        acc += hv * pW1[k * 32 + lane];
    }
    float u = fmaxf(acc + pb1[lane], 0.f);
    float pv = u * pW2[lane];
#pragma unroll
    for (int off = 16; off; off >>= 1) pv += __shfl_down_sync(0xffffffffu, pv, off);
    if (lane == 0) out[gw] = pv + pb2[0];
}

// ---------------- value head ----------------
__global__ void k_value(const float* __restrict__ vW1, const float* __restrict__ vb1,
                        const float* __restrict__ vW2, const float* __restrict__ vb2,
                        float* __restrict__ out, int n) {
    __shared__ float gm[HD];
    __shared__ float red[64];
    int t = threadIdx.x;
    if (t < HD) gm[t] = d_pool[t] / (float)n;
    __syncthreads();
    if (t < 64) {
        float acc = 0.f;
#pragma unroll 8
        for (int k = 0; k < 128; k++) acc += gm[k] * vW1[k * 64 + t];
        float u = fmaxf(acc + vb1[t], 0.f);
        red[t] = u * vW2[t];
    }
    __syncthreads();
    if (t == 0) {
        float s = 0.f;
        for (int i = 0; i < 64; i++) s += red[i];
        out[n] = tanhf(s + vb2[0]);
    }
}

// ---------------- launcher ----------------
extern "C" void kernel_launch(void* const* d_in, const int* in_sizes, int n_in,
                              void* d_out, int out_size) {
    const float* x  = (const float*)d_in[0];
    const int*   ei = (const int*)d_in[1];     // int32 (JAX x64-disabled)
    // d_in[2] batch: single graph, unused
    const float* in_W    = (const float*)d_in[3];
    // d_in[4] in_b cancels through BN
    const float* in_g    = (const float*)d_in[5];
    const float* in_beta = (const float*)d_in[6];
    const float* conv_W  = (const float*)d_in[7];
    // d_in[8] conv_b cancels through BN
    const float* bn_g    = (const float*)d_in[9];
    const float* bn_beta = (const float*)d_in[10];
    const float* pW1 = (const float*)d_in[11];
    const float* pb1 = (const float*)d_in[12];
    const float* pW2 = (const float*)d_in[13];
    const float* pb2 = (const float*)d_in[14];
    const float* vW1 = (const float*)d_in[15];
    const float* vb1 = (const float*)d_in[16];
    const float* vW2 = (const float*)d_in[17];
    const float* vb2 = (const float*)d_in[18];
    float* out = (float*)d_out;

    int n = in_sizes[0] / 5;
    int e = in_sizes[1] / 2;

    int nb   = (n + 255) / 256;
    int eb   = (e + 255) / 256;
    int nvb  = (n * 32 + 255) / 256;      // one thread per float4 of [N,128]
    int nblk = nb;
    int gemmb = (n + 127) / 128;
    int aggb  = (n + 15) / 16;

    // allow 85KB dynamic smem for the GEMM (idempotent; host-side, capture-safe)
    cudaFuncSetAttribute(k_gemm_tc, cudaFuncAttributeMaxDynamicSharedMemorySize, GEMM_SMEM);

    // Order chosen so the 4th launch (ncu capture point) is k_gemm_tc.
    k_init<<<nb, 256>>>(n);
    k_count<<<eb, 256>>>(ei, e);
    k_ingemm<<<nvb, 256>>>(x, in_W, in_g, in_beta, n);           // stats + finalize fused
    k_gemm_tc<<<gemmb, 256, GEMM_SMEM>>>(conv_W, n, 0);          // layer 0  <- profiled

    // CSR prep (independent of gemm; only gates agg)
    k_dinv<<<nb, 256>>>(n);
    k_scan1<<<nblk, 256>>>(n);
    k_scan2<<<1, 512>>>(nblk, n);
    k_scan3<<<nblk, 256>>>(n);
    k_fill<<<eb, 256>>>(ei, e);

    k_agg<<<aggb, 512>>>(bn_g, bn_beta, n);                      // layer 0 agg + finalize
    for (int l = 1; l < 6; l++) {
        k_gemm_tc<<<gemmb, 256, GEMM_SMEM>>>(conv_W + (size_t)l * HD * HD, n, 1);
        k_agg<<<aggb, 512>>>(bn_g + l * HD, bn_beta + l * HD, n);
    }

    // final apply (+pool fusion), heads
    k_apply_final<<<nvb, 256>>>(n);
    k_policy<<<nvb, 256>>>(pW1, pb1, pW2, pb2, out, n);
    k_value<<<1, 128>>>(vW1, vb1, vW2, vb2, out, n);
}